// round 1
// baseline (speedup 1.0000x reference)
#include <cuda_runtime.h>
#include <cstdint>

#define NN 100000
#define NE 800000
#define DIN 128
#define DH  128
#define DC  40

// ---------------- device scratch (no allocations allowed) ----------------
__device__ float g_agg1[(size_t)NN * DIN];   // layer-1 neighbor sums
__device__ float g_h   [(size_t)NN * DH];    // relu(layer1) output
__device__ float g_agg2[(size_t)NN * DH];    // layer-2 neighbor sums
__device__ float g_cnt [NN];                 // in-degree (float, exact < 2^24)
__device__ float g_inv [NN];                 // 1/max(cnt,1)
__device__ int   g_src [NE];
__device__ int   g_dst [NE];
__device__ int   g_is64;

// ---------------- edge dtype detection + conversion ----------------
// If edges are int64 (values < 100000), every odd 32-bit word is zero.
__global__ void detect_kernel(const unsigned int* __restrict__ w) {
    int nz = 0;
    for (int i = threadIdx.x; i < 2048; i += blockDim.x)
        nz |= (w[2 * i + 1] != 0u);
    nz = __syncthreads_or(nz);
    if (threadIdx.x == 0) g_is64 = (nz == 0) ? 1 : 0;
}

__global__ void convert_kernel(const void* __restrict__ ei) {
    int i = blockIdx.x * blockDim.x + threadIdx.x;
    if (i >= NE) return;
    if (g_is64) {
        const long long* p = (const long long*)ei;
        g_src[i] = (int)p[i];
        g_dst[i] = (int)p[NE + i];
    } else {
        const int* p = (const int*)ei;
        g_src[i] = p[i];
        g_dst[i] = p[NE + i];
    }
}

// ---------------- zero scratch ----------------
__global__ void zero_kernel() {
    size_t i = (size_t)blockIdx.x * blockDim.x + threadIdx.x;
    size_t stride = (size_t)gridDim.x * blockDim.x;
    const size_t n = (size_t)NN * DIN;
    for (size_t j = i; j < n; j += stride) { g_agg1[j] = 0.f; g_agg2[j] = 0.f; }
    for (size_t j = i; j < NN; j += stride) g_cnt[j] = 0.f;
}

// ---------------- scatter: one warp per edge, float4 lanes ----------------
// which==0: src feats from xin -> g_agg1, also count degrees
// which==1: src feats from xin -> g_agg2
__global__ void __launch_bounds__(256) scatter_kernel(const float* __restrict__ xin,
                                                      int which) {
    int gw   = (blockIdx.x * blockDim.x + threadIdx.x) >> 5;
    int lane = threadIdx.x & 31;
    if (gw >= NE) return;
    int s = g_src[gw];
    int d = g_dst[gw];
    float4 v = ((const float4*)xin)[(size_t)s * 32 + lane];
    float* agg = (which == 0) ? g_agg1 : g_agg2;
    float* p = agg + (size_t)d * 128 + lane * 4;
    asm volatile("red.global.add.v4.f32 [%0], {%1, %2, %3, %4};"
                 :: "l"(p), "f"(v.x), "f"(v.y), "f"(v.z), "f"(v.w) : "memory");
    if (which == 0 && lane == 0)
        atomicAdd(&g_cnt[d], 1.0f);
}

__global__ void inv_kernel() {
    int i = blockIdx.x * blockDim.x + threadIdx.x;
    if (i < NN) g_inv[i] = 1.0f / fmaxf(g_cnt[i], 1.0f);
}

// ---------------- fused dual GEMM: out = (agg*inv)@Wl + A2@Wr + b ----------------
// A1 (agg) and A2 are [rows, 128]; Wl/Wr are [128, NC]; out is [rows, NC].
// Block computes BM x BN tile; thread computes TM x TN microtile. K fixed 128.
template<int BM, int BN, int TM, int TN, int NC, int NT, bool RELU>
__global__ void __launch_bounds__(NT) gemm_kernel(const float* __restrict__ A1,
                                                  const float* __restrict__ A2,
                                                  const float* __restrict__ Wl,
                                                  const float* __restrict__ Wr,
                                                  const float* __restrict__ bias,
                                                  float* __restrict__ out) {
    constexpr int K  = 128;
    constexpr int KT = 16;
    __shared__ float sAm[KT][BM];
    __shared__ float sAx[KT][BM];
    __shared__ float sWl[KT][BN];
    __shared__ float sWr[KT][BN];

    const int tid = threadIdx.x;
    const int nx  = BN / TN;             // threads along cols
    const int tx  = tid % nx;
    const int ty  = tid / nx;
    const int row0 = blockIdx.x * BM;

    float acc[TM][TN];
    #pragma unroll
    for (int i = 0; i < TM; i++)
        #pragma unroll
        for (int j = 0; j < TN; j++) acc[i][j] = 0.f;

    for (int k0 = 0; k0 < K; k0 += KT) {
        // load A tiles (transposed to [k][row]) with mean scaling on A1
        for (int idx = tid; idx < KT * BM; idx += NT) {
            int r  = idx / KT;
            int kk = idx % KT;
            int row = row0 + r;
            float a1 = 0.f, a2 = 0.f;
            if (row < NN) {
                size_t off = (size_t)row * K + k0 + kk;
                a1 = A1[off] * g_inv[row];
                a2 = A2[off];
            }
            sAm[kk][r] = a1;
            sAx[kk][r] = a2;
        }
        // load W tiles [k][col], zero-pad cols >= NC
        for (int idx = tid; idx < KT * BN; idx += NT) {
            int kk = idx / BN;
            int c  = idx % BN;
            float wl = 0.f, wr = 0.f;
            if (c < NC) {
                size_t off = (size_t)(k0 + kk) * NC + c;
                wl = Wl[off];
                wr = Wr[off];
            }
            sWl[kk][c] = wl;
            sWr[kk][c] = wr;
        }
        __syncthreads();

        #pragma unroll
        for (int kk = 0; kk < KT; kk++) {
            float am[TM], ax[TM], wl[TN], wr[TN];
            #pragma unroll
            for (int i = 0; i < TM; i++) {
                am[i] = sAm[kk][ty * TM + i];
                ax[i] = sAx[kk][ty * TM + i];
            }
            #pragma unroll
            for (int j = 0; j < TN; j++) {
                wl[j] = sWl[kk][tx * TN + j];
                wr[j] = sWr[kk][tx * TN + j];
            }
            #pragma unroll
            for (int i = 0; i < TM; i++)
                #pragma unroll
                for (int j = 0; j < TN; j++)
                    acc[i][j] += am[i] * wl[j] + ax[i] * wr[j];
        }
        __syncthreads();
    }

    #pragma unroll
    for (int i = 0; i < TM; i++) {
        int row = row0 + ty * TM + i;
        if (row >= NN) continue;
        #pragma unroll
        for (int j = 0; j < TN; j++) {
            int c = tx * TN + j;
            if (c < NC) {
                float v = acc[i][j] + bias[c];
                if (RELU) v = fmaxf(v, 0.f);
                out[(size_t)row * NC + c] = v;
            }
        }
    }
}

// ---------------- launcher ----------------
extern "C" void kernel_launch(void* const* d_in, const int* in_sizes, int n_in,
                              void* d_out, int out_size) {
    const float* x    = (const float*)d_in[0];
    const void*  edge = d_in[1];
    const float* W1l  = (const float*)d_in[2];
    const float* W1r  = (const float*)d_in[3];
    const float* b1   = (const float*)d_in[4];
    const float* W2l  = (const float*)d_in[5];
    const float* W2r  = (const float*)d_in[6];
    const float* b2   = (const float*)d_in[7];
    float* out = (float*)d_out;

    // resolve device-global addresses (host can't reference __device__ directly)
    float *agg1, *h, *agg2;
    cudaGetSymbolAddress((void**)&agg1, g_agg1);
    cudaGetSymbolAddress((void**)&h,    g_h);
    cudaGetSymbolAddress((void**)&agg2, g_agg2);

    detect_kernel<<<1, 256>>>((const unsigned int*)edge);
    convert_kernel<<<(NE + 255) / 256, 256>>>(edge);
    zero_kernel<<<4096, 256>>>();

    // layer 1: aggregate x, then h = relu(mean@W1l + x@W1r + b1)
    scatter_kernel<<<NE / 8, 256>>>(x, 0);
    inv_kernel<<<(NN + 255) / 256, 256>>>();
    gemm_kernel<128, 128, 8, 8, 128, 256, true>
        <<<(NN + 127) / 128, 256>>>(agg1, x, W1l, W1r, b1, h);

    // layer 2: aggregate h, then out = mean2@W2l + h@W2r + b2
    scatter_kernel<<<NE / 8, 256>>>(h, 1);
    gemm_kernel<128, 48, 4, 4, 40, 384, false>
        <<<(NN + 127) / 128, 384>>>(agg2, h, W2l, W2r, b2, out);
}

// round 2
// speedup vs baseline: 1.6922x; 1.6922x over previous
#include <cuda_runtime.h>
#include <cstdint>

#define NN 100000
#define NE 800000

// ---------------- device scratch ----------------
__device__ float g_agg1[(size_t)NN * 128];   // layer-1 neighbor sums
__device__ float g_h   [(size_t)NN * 128];   // relu(layer1)
__device__ float g_t2  [(size_t)NN * 40];    // h @ W2l
__device__ float g_r2  [(size_t)NN * 40];    // h @ W2r
__device__ float g_aggt[(size_t)NN * 40];    // scattered t2
__device__ float g_cnt [NN];
__device__ float g_inv [NN];
__device__ int   g_src [NE];
__device__ int   g_dst [NE];
__device__ int   g_is64;

// ---------------- packed f32x2 helpers ----------------
__device__ __forceinline__ unsigned long long pk2(float a, float b) {
    unsigned long long r;
    asm("mov.b64 %0, {%1, %2};" : "=l"(r) : "f"(a), "f"(b));
    return r;
}
__device__ __forceinline__ void fma2(unsigned long long& d,
                                     unsigned long long a, unsigned long long b) {
    asm("fma.rn.f32x2 %0, %1, %2, %3;" : "=l"(d) : "l"(a), "l"(b), "l"(d));
}
__device__ __forceinline__ float2 up2(unsigned long long v) {
    float2 f;
    asm("mov.b64 {%0, %1}, %2;" : "=f"(f.x), "=f"(f.y) : "l"(v));
    return f;
}

// ---------------- edge dtype detection ----------------
__global__ void detect_kernel(const unsigned int* __restrict__ w) {
    int nz = 0;
    for (int i = threadIdx.x; i < 2048; i += blockDim.x)
        nz |= (w[2 * i + 1] != 0u);
    nz = __syncthreads_or(nz);
    if (threadIdx.x == 0) g_is64 = (nz == 0) ? 1 : 0;
}

// ---------------- zero scratch ----------------
__global__ void zero_kernel() {
    size_t i = (size_t)blockIdx.x * blockDim.x + threadIdx.x;
    size_t stride = (size_t)gridDim.x * blockDim.x;
    float4 z = {0.f, 0.f, 0.f, 0.f};
    float4* a1 = (float4*)g_agg1;
    float4* at = (float4*)g_aggt;
    for (size_t j = i; j < (size_t)NN * 32; j += stride) a1[j] = z;
    for (size_t j = i; j < (size_t)NN * 10; j += stride) at[j] = z;
    for (size_t j = i; j < NN; j += stride) g_cnt[j] = 0.f;
}

// ---------------- convert + degree count ----------------
__global__ void convert_kernel(const void* __restrict__ ei) {
    int i = blockIdx.x * blockDim.x + threadIdx.x;
    if (i >= NE) return;
    int s, d;
    if (g_is64) {
        const long long* p = (const long long*)ei;
        s = (int)p[i]; d = (int)p[NE + i];
    } else {
        const int* p = (const int*)ei;
        s = p[i]; d = p[NE + i];
    }
    g_src[i] = s;
    g_dst[i] = d;
    atomicAdd(&g_cnt[d], 1.0f);
}

__global__ void inv_kernel() {
    int i = blockIdx.x * blockDim.x + threadIdx.x;
    if (i < NN) g_inv[i] = 1.0f / fmaxf(g_cnt[i], 1.0f);
}

// ---------------- scatter layer 1: warp per edge, 128 floats ----------------
__global__ void __launch_bounds__(256) scatter1_kernel(const float* __restrict__ xin) {
    int gw   = (blockIdx.x * blockDim.x + threadIdx.x) >> 5;
    int lane = threadIdx.x & 31;
    if (gw >= NE) return;
    int s = g_src[gw];
    int d = g_dst[gw];
    float4 v = ((const float4*)xin)[(size_t)s * 32 + lane];
    float* p = g_agg1 + (size_t)d * 128 + lane * 4;
    asm volatile("red.global.add.v4.f32 [%0], {%1, %2, %3, %4};"
                 :: "l"(p), "f"(v.x), "f"(v.y), "f"(v.z), "f"(v.w) : "memory");
}

// ---------------- scatter layer 2: thread per (edge, 4-float chunk) ----------------
__global__ void __launch_bounds__(256) scatter2_kernel() {
    int i = blockIdx.x * blockDim.x + threadIdx.x;
    if (i >= NE * 10) return;
    int e = i / 10;
    int c = i - e * 10;
    int s = g_src[e];
    int d = g_dst[e];
    float4 v = ((const float4*)g_t2)[(size_t)s * 10 + c];
    float* p = g_aggt + (size_t)d * 40 + c * 4;
    asm volatile("red.global.add.v4.f32 [%0], {%1, %2, %3, %4};"
                 :: "l"(p), "f"(v.x), "f"(v.y), "f"(v.z), "f"(v.w) : "memory");
}

// ---------------- layer-1 dual GEMM: h = relu((agg1*inv)@Wl + x@Wr + b) ----------------
// BM=128, BN=128, TM=8, TN=8, KT=16, 256 threads
__global__ void __launch_bounds__(256) gemm1_kernel(const float* __restrict__ X,
                                                    const float* __restrict__ Wl,
                                                    const float* __restrict__ Wr,
                                                    const float* __restrict__ bias) {
    constexpr int KT = 16, BM = 128, BN = 128, TM = 8, TN = 8;
    __shared__ float sA1[BM][KT];
    __shared__ float sA2[BM][KT];
    __shared__ float sWl[KT][BN];
    __shared__ float sWr[KT][BN];

    const int tid = threadIdx.x;
    const int tx = tid & 15;          // 16 cols of threads
    const int ty = tid >> 4;          // 16 rows of threads
    const int row0 = blockIdx.x * BM;

    unsigned long long acc[TM][TN / 2];
    #pragma unroll
    for (int i = 0; i < TM; i++)
        #pragma unroll
        for (int j = 0; j < TN / 2; j++) acc[i][j] = 0ull;

    for (int k0 = 0; k0 < 128; k0 += KT) {
        // A tiles: 512 float4 loads per matrix, 2 per thread
        #pragma unroll
        for (int t = 0; t < 2; t++) {
            int idx = tid + t * 256;          // 0..511
            int r = idx >> 2, kv = idx & 3;
            int row = row0 + r;
            float4 a1 = {0.f,0.f,0.f,0.f}, a2 = a1;
            if (row < NN) {
                size_t off = (size_t)row * 128 + k0 + kv * 4;
                a1 = *(const float4*)(g_agg1 + off);
                float s = g_inv[row];
                a1.x *= s; a1.y *= s; a1.z *= s; a1.w *= s;
                a2 = *(const float4*)(X + off);
            }
            *(float4*)&sA1[r][kv * 4] = a1;
            *(float4*)&sA2[r][kv * 4] = a2;
        }
        // W tiles: 512 float4 per matrix
        #pragma unroll
        for (int t = 0; t < 2; t++) {
            int idx = tid + t * 256;          // 0..511
            int kk = idx >> 5, cv = idx & 31; // kk 0..15, cv 0..31
            size_t off = (size_t)(k0 + kk) * 128 + cv * 4;
            *(float4*)&sWl[kk][cv * 4] = *(const float4*)(Wl + off);
            *(float4*)&sWr[kk][cv * 4] = *(const float4*)(Wr + off);
        }
        __syncthreads();

        #pragma unroll
        for (int kk = 0; kk < KT; kk++) {
            unsigned long long wl[TN / 2], wr[TN / 2];
            const unsigned long long* pl = (const unsigned long long*)&sWl[kk][tx * TN];
            const unsigned long long* pr = (const unsigned long long*)&sWr[kk][tx * TN];
            #pragma unroll
            for (int j = 0; j < TN / 2; j++) { wl[j] = pl[j]; wr[j] = pr[j]; }
            #pragma unroll
            for (int i = 0; i < TM; i++) {
                float a1 = sA1[ty * TM + i][kk];
                float a2 = sA2[ty * TM + i][kk];
                unsigned long long p1 = pk2(a1, a1);
                unsigned long long p2 = pk2(a2, a2);
                #pragma unroll
                for (int j = 0; j < TN / 2; j++) {
                    fma2(acc[i][j], p1, wl[j]);
                    fma2(acc[i][j], p2, wr[j]);
                }
            }
        }
        __syncthreads();
    }

    #pragma unroll
    for (int i = 0; i < TM; i++) {
        int row = row0 + ty * TM + i;
        if (row >= NN) continue;
        #pragma unroll
        for (int j = 0; j < TN / 2; j++) {
            int c = tx * TN + 2 * j;
            float2 v = up2(acc[i][j]);
            v.x = fmaxf(v.x + bias[c], 0.f);
            v.y = fmaxf(v.y + bias[c + 1], 0.f);
            *(float2*)(g_h + (size_t)row * 128 + c) = v;
        }
    }
}

// ---------------- layer-2 dual GEMM: t2 = h@W2l, r2 = h@W2r ----------------
// BM=128, BN=40, TM=8, TN=4, KT=16, 160 threads (nx=10, ny=16)
__global__ void __launch_bounds__(160) gemm2_kernel(const float* __restrict__ Wl,
                                                    const float* __restrict__ Wr) {
    constexpr int KT = 16, BM = 128, BN = 40, TM = 8, TN = 4;
    __shared__ float sA[BM][KT];
    __shared__ float sWl[KT][BN];
    __shared__ float sWr[KT][BN];

    const int tid = threadIdx.x;
    const int tx = tid % 10;
    const int ty = tid / 10;
    const int row0 = blockIdx.x * BM;

    unsigned long long acc1[TM][TN / 2], acc2[TM][TN / 2];
    #pragma unroll
    for (int i = 0; i < TM; i++)
        #pragma unroll
        for (int j = 0; j < TN / 2; j++) { acc1[i][j] = 0ull; acc2[i][j] = 0ull; }

    for (int k0 = 0; k0 < 128; k0 += KT) {
        // A tile: 512 float4
        for (int idx = tid; idx < BM * KT / 4; idx += 160) {
            int r = idx >> 2, kv = idx & 3;
            int row = row0 + r;
            float4 a = {0.f,0.f,0.f,0.f};
            if (row < NN)
                a = *(const float4*)(g_h + (size_t)row * 128 + k0 + kv * 4);
            *(float4*)&sA[r][kv * 4] = a;
        }
        // W tiles: 160 float4 each, exactly one per thread
        {
            int kk = tid / 10, cv = tid % 10;
            size_t off = (size_t)(k0 + kk) * 40 + cv * 4;
            *(float4*)&sWl[kk][cv * 4] = *(const float4*)(Wl + off);
            *(float4*)&sWr[kk][cv * 4] = *(const float4*)(Wr + off);
        }
        __syncthreads();

        #pragma unroll
        for (int kk = 0; kk < KT; kk++) {
            unsigned long long wl[TN / 2], wr[TN / 2];
            const unsigned long long* pl = (const unsigned long long*)&sWl[kk][tx * TN];
            const unsigned long long* pr = (const unsigned long long*)&sWr[kk][tx * TN];
            #pragma unroll
            for (int j = 0; j < TN / 2; j++) { wl[j] = pl[j]; wr[j] = pr[j]; }
            #pragma unroll
            for (int i = 0; i < TM; i++) {
                float a = sA[ty * TM + i][kk];
                unsigned long long pa = pk2(a, a);
                #pragma unroll
                for (int j = 0; j < TN / 2; j++) {
                    fma2(acc1[i][j], pa, wl[j]);
                    fma2(acc2[i][j], pa, wr[j]);
                }
            }
        }
        __syncthreads();
    }

    #pragma unroll
    for (int i = 0; i < TM; i++) {
        int row = row0 + ty * TM + i;
        if (row >= NN) continue;
        #pragma unroll
        for (int j = 0; j < TN / 2; j++) {
            int c = tx * TN + 2 * j;
            *(float2*)(g_t2 + (size_t)row * 40 + c) = up2(acc1[i][j]);
            *(float2*)(g_r2 + (size_t)row * 40 + c) = up2(acc2[i][j]);
        }
    }
}

// ---------------- final: out = aggt*inv + r2 + b2 ----------------
__global__ void __launch_bounds__(256) final_kernel(const float* __restrict__ b2,
                                                    float* __restrict__ out) {
    int i = blockIdx.x * blockDim.x + threadIdx.x;
    if (i >= NN * 10) return;
    int n = i / 10;
    int c = i - n * 10;
    float s = g_inv[n];
    float4 a = ((const float4*)g_aggt)[i];
    float4 r = ((const float4*)g_r2)[i];
    float4 b = ((const float4*)b2)[c];
    float4 o;
    o.x = a.x * s + r.x + b.x;
    o.y = a.y * s + r.y + b.y;
    o.z = a.z * s + r.z + b.z;
    o.w = a.w * s + r.w + b.w;
    ((float4*)out)[i] = o;
}

// ---------------- launcher ----------------
extern "C" void kernel_launch(void* const* d_in, const int* in_sizes, int n_in,
                              void* d_out, int out_size) {
    const float* x    = (const float*)d_in[0];
    const void*  edge = d_in[1];
    const float* W1l  = (const float*)d_in[2];
    const float* W1r  = (const float*)d_in[3];
    const float* b1   = (const float*)d_in[4];
    const float* W2l  = (const float*)d_in[5];
    const float* W2r  = (const float*)d_in[6];
    const float* b2   = (const float*)d_in[7];
    float* out = (float*)d_out;

    detect_kernel<<<1, 256>>>((const unsigned int*)edge);
    zero_kernel<<<2048, 256>>>();
    convert_kernel<<<(NE + 255) / 256, 256>>>(edge);
    inv_kernel<<<(NN + 255) / 256, 256>>>();

    // layer 1
    scatter1_kernel<<<NE / 8, 256>>>(x);
    gemm1_kernel<<<(NN + 127) / 128, 256>>>(x, W1l, W1r, b1);

    // layer 2 (transform-then-aggregate)
    gemm2_kernel<<<(NN + 127) / 128, 160>>>(W2l, W2r);
    scatter2_kernel<<<(NE * 10 + 255) / 256, 256>>>();
    final_kernel<<<(NN * 10 + 255) / 256, 256>>>(b2, out);
}

// round 4
// speedup vs baseline: 3.0517x; 1.8034x over previous
#include <cuda_runtime.h>
#include <cstdint>

#define NN 100000
#define NE 800000
#define LDA 36

// ---------------- device scratch ----------------
__device__ float g_agg1[(size_t)NN * 128];
__device__ float g_h   [(size_t)NN * 128];
__device__ float g_t2  [(size_t)NN * 40];
__device__ float g_r2  [(size_t)NN * 40];
__device__ float g_aggt[(size_t)NN * 40];
__device__ float g_cnt [NN];
__device__ float g_inv [NN];
__device__ int   g_src [NE];
__device__ int   g_dst [NE];
__device__ int   g_is64;
__device__ float g_W1t[128 * 256];   // B operand layer1: [n=128][k=256], tf32-rounded
__device__ float g_W2t[80 * 128];    // B operand layer2: [n=80][k=128], tf32-rounded

// ---------------- helpers ----------------
__device__ __forceinline__ float f2tf(float f) {
    unsigned int r;
    asm("cvt.rna.tf32.f32 %0, %1;" : "=r"(r) : "f"(f));
    return __uint_as_float(r);
}
__device__ __forceinline__ void cp16(uint32_t dst, const void* src) {
    asm volatile("cp.async.cg.shared.global [%0], [%1], 16;" :: "r"(dst), "l"(src));
}
__device__ __forceinline__ void mma8(float* c, float a0, float a1, float a2, float a3,
                                     float b0, float b1) {
    asm volatile("mma.sync.aligned.m16n8k8.row.col.f32.tf32.tf32.f32 "
        "{%0,%1,%2,%3}, {%4,%5,%6,%7}, {%8,%9}, {%0,%1,%2,%3};"
        : "+f"(c[0]), "+f"(c[1]), "+f"(c[2]), "+f"(c[3])
        : "r"(__float_as_uint(a0)), "r"(__float_as_uint(a1)),
          "r"(__float_as_uint(a2)), "r"(__float_as_uint(a3)),
          "r"(__float_as_uint(b0)), "r"(__float_as_uint(b1)));
}

// ---------------- small setup kernels ----------------
__global__ void detect_kernel(const unsigned int* __restrict__ w) {
    int nz = 0;
    for (int i = threadIdx.x; i < 2048; i += blockDim.x)
        nz |= (w[2 * i + 1] != 0u);
    nz = __syncthreads_or(nz);
    if (threadIdx.x == 0) g_is64 = (nz == 0) ? 1 : 0;
}

__global__ void zero_kernel() {
    size_t i = (size_t)blockIdx.x * blockDim.x + threadIdx.x;
    size_t stride = (size_t)gridDim.x * blockDim.x;
    float4 z = {0.f, 0.f, 0.f, 0.f};
    float4* a1 = (float4*)g_agg1;
    float4* at = (float4*)g_aggt;
    for (size_t j = i; j < (size_t)NN * 32; j += stride) a1[j] = z;
    for (size_t j = i; j < (size_t)NN * 10; j += stride) at[j] = z;
    for (size_t j = i; j < NN; j += stride) g_cnt[j] = 0.f;
}

__global__ void convert_kernel(const void* __restrict__ ei) {
    int i = blockIdx.x * blockDim.x + threadIdx.x;
    if (i >= NE) return;
    int s, d;
    if (g_is64) {
        const long long* p = (const long long*)ei;
        s = (int)p[i]; d = (int)p[NE + i];
    } else {
        const int* p = (const int*)ei;
        s = p[i]; d = p[NE + i];
    }
    g_src[i] = s;
    g_dst[i] = d;
    atomicAdd(&g_cnt[d], 1.0f);
}

__global__ void inv_kernel() {
    int i = blockIdx.x * blockDim.x + threadIdx.x;
    if (i < NN) g_inv[i] = 1.0f / fmaxf(g_cnt[i], 1.0f);
}

// transpose weights to B-operand layout [n][k], tf32-rounded
__global__ void prep_w1(const float* __restrict__ Wl, const float* __restrict__ Wr) {
    int tid = blockIdx.x * blockDim.x + threadIdx.x;   // 32768
    int k = tid >> 7, n = tid & 127;
    float v = (k < 128) ? Wl[k * 128 + n] : Wr[(k - 128) * 128 + n];
    g_W1t[n * 256 + k] = f2tf(v);
}

__global__ void prep_w2(const float* __restrict__ Wl, const float* __restrict__ Wr) {
    int tid = blockIdx.x * blockDim.x + threadIdx.x;   // 10240
    int k = tid / 80, n = tid - k * 80;
    float v = (n < 40) ? Wl[k * 40 + n] : Wr[k * 40 + (n - 40)];
    g_W2t[n * 128 + k] = f2tf(v);
}

// ---------------- scatters ----------------
__global__ void __launch_bounds__(256) scatter1_kernel(const float* __restrict__ xin) {
    int gw   = (blockIdx.x * blockDim.x + threadIdx.x) >> 5;
    int lane = threadIdx.x & 31;
    if (gw >= NE) return;
    int s = g_src[gw];
    int d = g_dst[gw];
    float4 v = ((const float4*)xin)[(size_t)s * 32 + lane];
    float* p = g_agg1 + (size_t)d * 128 + lane * 4;
    asm volatile("red.global.add.v4.f32 [%0], {%1, %2, %3, %4};"
                 :: "l"(p), "f"(v.x), "f"(v.y), "f"(v.z), "f"(v.w) : "memory");
}

__global__ void __launch_bounds__(256) scatter2_kernel() {
    int i = blockIdx.x * blockDim.x + threadIdx.x;
    if (i >= NE * 10) return;
    int e = i / 10;
    int c = i - e * 10;
    int s = g_src[e];
    int d = g_dst[e];
    float4 v = ((const float4*)g_t2)[(size_t)s * 10 + c];
    float* p = g_aggt + (size_t)d * 40 + c * 4;
    asm volatile("red.global.add.v4.f32 [%0], {%1, %2, %3, %4};"
                 :: "l"(p), "f"(v.x), "f"(v.y), "f"(v.z), "f"(v.w) : "memory");
}

// ---------------- GEMM1 (mma.sync tf32): h = relu([mean|x] @ W1cat + b1) ----------------
// CTA 128x128, K=256 (phase 0: agg1*inv, phase 1: x). 8 warps: wm=wid&3 (32 rows), wn=wid>>2 (64 cols)
#define G1_SMEM (2 * 128 * LDA * 4 * 2 + 512)
__global__ void __launch_bounds__(256) gemm1_mma(const float* __restrict__ X,
                                                 const float* __restrict__ bias) {
    extern __shared__ float smem[];
    float* sA = smem;                       // 2 x 128 x LDA
    float* sB = sA + 2 * 128 * LDA;         // 2 x 128 x LDA
    float* sBias = sB + 2 * 128 * LDA;      // 128

    const int tid = threadIdx.x, lane = tid & 31, wid = tid >> 5;
    const int wm = wid & 3, wn = wid >> 2;
    const int row0 = blockIdx.x * 128;
    if (tid < 128) sBias[tid] = bias[tid];

    float acc[2][8][4];
    #pragma unroll
    for (int mt = 0; mt < 2; mt++)
        #pragma unroll
        for (int nt = 0; nt < 8; nt++)
            #pragma unroll
            for (int q = 0; q < 4; q++) acc[mt][nt][q] = 0.f;

    float iv[2][2];
    #pragma unroll
    for (int mt = 0; mt < 2; mt++) {
        int r = row0 + wm * 32 + mt * 16 + (lane >> 2);
        int ra = r < NN ? r : NN - 1;
        int rb = (r + 8) < NN ? (r + 8) : NN - 1;
        iv[mt][0] = g_inv[ra];
        iv[mt][1] = g_inv[rb];
    }

    auto issue = [&](int c) {
        const float* asrc = (c < 4) ? g_agg1 : X;
        const int k0 = (c & 3) * 32;
        float* dA = sA + (c & 1) * (128 * LDA);
        float* dB = sB + (c & 1) * (128 * LDA);
        #pragma unroll
        for (int t = 0; t < 4; t++) {
            int i = tid + t * 256;
            int r = i >> 3, seg = i & 7;
            int grow = row0 + r;
            if (grow > NN - 1) grow = NN - 1;
            cp16((uint32_t)__cvta_generic_to_shared(dA + r * LDA + seg * 4),
                 asrc + (size_t)grow * 128 + k0 + seg * 4);
            cp16((uint32_t)__cvta_generic_to_shared(dB + r * LDA + seg * 4),
                 g_W1t + r * 256 + c * 32 + seg * 4);
        }
        asm volatile("cp.async.commit_group;" ::: "memory");
    };

    issue(0);
    for (int c = 0; c < 8; c++) {
        if (c < 7) {
            issue(c + 1);
            asm volatile("cp.async.wait_group 1;" ::: "memory");
        } else {
            asm volatile("cp.async.wait_group 0;" ::: "memory");
        }
        __syncthreads();
        const float* A = sA + (c & 1) * (128 * LDA);
        const float* B = sB + (c & 1) * (128 * LDA);
        const bool ph0 = (c < 4);
        #pragma unroll
        for (int ks = 0; ks < 4; ks++) {
            const int bk = ks * 8 + (lane & 3);
            float b0[8], b1[8];
            #pragma unroll
            for (int nt = 0; nt < 8; nt++) {
                int n = wn * 64 + nt * 8 + (lane >> 2);
                b0[nt] = B[n * LDA + bk];
                b1[nt] = B[n * LDA + bk + 4];
            }
            #pragma unroll
            for (int mt = 0; mt < 2; mt++) {
                int r = wm * 32 + mt * 16 + (lane >> 2);
                float a0 = A[r * LDA + bk];
                float a1 = A[(r + 8) * LDA + bk];
                float a2 = A[r * LDA + bk + 4];
                float a3 = A[(r + 8) * LDA + bk + 4];
                if (ph0) {
                    a0 *= iv[mt][0]; a1 *= iv[mt][1];
                    a2 *= iv[mt][0]; a3 *= iv[mt][1];
                }
                #pragma unroll
                for (int nt = 0; nt < 8; nt++)
                    mma8(acc[mt][nt], a0, a1, a2, a3, b0[nt], b1[nt]);
            }
        }
        __syncthreads();
    }

    #pragma unroll
    for (int mt = 0; mt < 2; mt++) {
        int r = row0 + wm * 32 + mt * 16 + (lane >> 2);
        #pragma unroll
        for (int nt = 0; nt < 8; nt++) {
            int cb = wn * 64 + nt * 8 + 2 * (lane & 3);
            if (r < NN) {
                float2 v;
                v.x = fmaxf(acc[mt][nt][0] + sBias[cb], 0.f);
                v.y = fmaxf(acc[mt][nt][1] + sBias[cb + 1], 0.f);
                *(float2*)(g_h + (size_t)r * 128 + cb) = v;
            }
            if (r + 8 < NN) {
                float2 v;
                v.x = fmaxf(acc[mt][nt][2] + sBias[cb], 0.f);
                v.y = fmaxf(acc[mt][nt][3] + sBias[cb + 1], 0.f);
                *(float2*)(g_h + (size_t)(r + 8) * 128 + cb) = v;
            }
        }
    }
}

// ---------------- GEMM2 (mma.sync tf32): [t2|r2] = h @ W2cat, N=80, K=128 ----------------
// CTA 128x80. 8 warps: wid -> 16 rows each, all 80 cols (NT=10).
#define G2_SMEM ((2 * 128 * LDA + 2 * 80 * LDA) * 4)
__global__ void __launch_bounds__(256) gemm2_mma() {
    extern __shared__ float smem[];
    float* sA = smem;                       // 2 x 128 x LDA
    float* sB = sA + 2 * 128 * LDA;         // 2 x 80 x LDA

    const int tid = threadIdx.x, lane = tid & 31, wid = tid >> 5;
    const int row0 = blockIdx.x * 128;

    float acc[10][4];
    #pragma unroll
    for (int nt = 0; nt < 10; nt++)
        #pragma unroll
        for (int q = 0; q < 4; q++) acc[nt][q] = 0.f;

    auto issue = [&](int c) {
        const int k0 = c * 32;
        float* dA = sA + (c & 1) * (128 * LDA);
        float* dB = sB + (c & 1) * (80 * LDA);
        #pragma unroll
        for (int t = 0; t < 4; t++) {
            int i = tid + t * 256;
            int r = i >> 3, seg = i & 7;
            int grow = row0 + r;
            if (grow > NN - 1) grow = NN - 1;
            cp16((uint32_t)__cvta_generic_to_shared(dA + r * LDA + seg * 4),
                 g_h + (size_t)grow * 128 + k0 + seg * 4);
        }
        #pragma unroll
        for (int t = 0; t < 3; t++) {
            int i = tid + t * 256;
            if (i < 640) {
                int r = i >> 3, seg = i & 7;
                cp16((uint32_t)__cvta_generic_to_shared(dB + r * LDA + seg * 4),
                     g_W2t + r * 128 + k0 + seg * 4);
            }
        }
        asm volatile("cp.async.commit_group;" ::: "memory");
    };

    issue(0);
    for (int c = 0; c < 4; c++) {
        if (c < 3) {
            issue(c + 1);
            asm volatile("cp.async.wait_group 1;" ::: "memory");
        } else {
            asm volatile("cp.async.wait_group 0;" ::: "memory");
        }
        __syncthreads();
        const float* A = sA + (c & 1) * (128 * LDA);
        const float* B = sB + (c & 1) * (80 * LDA);
        #pragma unroll
        for (int ks = 0; ks < 4; ks++) {
            const int bk = ks * 8 + (lane & 3);
            float b0[10], b1[10];
            #pragma unroll
            for (int nt = 0; nt < 10; nt++) {
                int n = nt * 8 + (lane >> 2);
                b0[nt] = B[n * LDA + bk];
                b1[nt] = B[n * LDA + bk + 4];
            }
            int r = wid * 16 + (lane >> 2);
            float a0 = A[r * LDA + bk];
            float a1 = A[(r + 8) * LDA + bk];
            float a2 = A[r * LDA + bk + 4];
            float a3 = A[(r + 8) * LDA + bk + 4];
            #pragma unroll
            for (int nt = 0; nt < 10; nt++)
                mma8(acc[nt], a0, a1, a2, a3, b0[nt], b1[nt]);
        }
        __syncthreads();
    }

    int r = row0 + wid * 16 + (lane >> 2);
    #pragma unroll
    for (int nt = 0; nt < 10; nt++) {
        int cb = nt * 8 + 2 * (lane & 3);
        float* base0 = (cb < 40) ? g_t2 + (size_t)r * 40 + cb
                                 : g_r2 + (size_t)r * 40 + (cb - 40);
        float* base1 = (cb < 40) ? g_t2 + (size_t)(r + 8) * 40 + cb
                                 : g_r2 + (size_t)(r + 8) * 40 + (cb - 40);
        if (r < NN)     *(float2*)base0 = make_float2(acc[nt][0], acc[nt][1]);
        if (r + 8 < NN) *(float2*)base1 = make_float2(acc[nt][2], acc[nt][3]);
    }
}

// ---------------- final: out = aggt*inv + r2 + b2 ----------------
__global__ void __launch_bounds__(256) final_kernel(const float* __restrict__ b2,
                                                    float* __restrict__ out) {
    int i = blockIdx.x * blockDim.x + threadIdx.x;
    if (i >= NN * 10) return;
    int n = i / 10;
    int c = i - n * 10;
    float s = g_inv[n];
    float4 a = ((const float4*)g_aggt)[i];
    float4 r = ((const float4*)g_r2)[i];
    float4 b = ((const float4*)b2)[c];
    float4 o;
    o.x = a.x * s + r.x + b.x;
    o.y = a.y * s + r.y + b.y;
    o.z = a.z * s + r.z + b.z;
    o.w = a.w * s + r.w + b.w;
    ((float4*)out)[i] = o;
}

// ---------------- launcher ----------------
extern "C" void kernel_launch(void* const* d_in, const int* in_sizes, int n_in,
                              void* d_out, int out_size) {
    const float* x    = (const float*)d_in[0];
    const void*  edge = d_in[1];
    const float* W1l  = (const float*)d_in[2];
    const float* W1r  = (const float*)d_in[3];
    const float* b1   = (const float*)d_in[4];
    const float* W2l  = (const float*)d_in[5];
    const float* W2r  = (const float*)d_in[6];
    const float* b2   = (const float*)d_in[7];
    float* out = (float*)d_out;

    static int attr_done = 0;
    if (!attr_done) {
        cudaFuncSetAttribute(gemm1_mma, cudaFuncAttributeMaxDynamicSharedMemorySize, G1_SMEM);
        cudaFuncSetAttribute(gemm2_mma, cudaFuncAttributeMaxDynamicSharedMemorySize, G2_SMEM);
        attr_done = 1;
    }

    detect_kernel<<<1, 256>>>((const unsigned int*)edge);
    zero_kernel<<<2048, 256>>>();
    convert_kernel<<<(NE + 255) / 256, 256>>>(edge);
    inv_kernel<<<(NN + 255) / 256, 256>>>();
    prep_w1<<<128, 256>>>(W1l, W1r);
    prep_w2<<<40, 256>>>(W2l, W2r);

    const int nblk = (NN + 127) / 128;   // 782
    scatter1_kernel<<<NE / 8, 256>>>(x);
    gemm1_mma<<<nblk, 256, G1_SMEM>>>(x, b1);
    gemm2_mma<<<nblk, 256, G2_SMEM>>>();
    scatter2_kernel<<<(NE * 10 + 255) / 256, 256>>>();
    final_kernel<<<(NN * 10 + 255) / 256, 256>>>(b2, out);
}

// round 5
// speedup vs baseline: 4.0069x; 1.3130x over previous
#include <cuda_runtime.h>
#include <cstdint>

#define NN 100000
#define NE 800000
#define LDA 36

// ---------------- device scratch ----------------
__device__ float g_mean[(size_t)NN * 128];   // mean-aggregated x
__device__ float g_h   [(size_t)NN * 128];   // relu(layer1)
__device__ float g_t2  [(size_t)NN * 40];    // h @ W2l
__device__ float g_r2  [(size_t)NN * 40];    // h @ W2r
__device__ int   g_icnt[NN];
__device__ float g_inv [NN];
__device__ int   g_rowptr[NN];
__device__ int   g_cursor[NN];
__device__ int   g_adj [NE];
__device__ int   g_src [NE];
__device__ int   g_dst [NE];
__device__ int   g_bsum[512];
__device__ int   g_boff[512];
__device__ int   g_is64;
__device__ float g_W1t[128 * 256];   // B layer1: [n=128][k=256], tf32-rna
__device__ float g_W2t[80 * 128];    // B layer2: [n=80][k=128], tf32-rna

// ---------------- helpers ----------------
__device__ __forceinline__ float f2tf(float f) {
    unsigned int r;
    asm("cvt.rna.tf32.f32 %0, %1;" : "=r"(r) : "f"(f));
    return __uint_as_float(r);
}
__device__ __forceinline__ void cp16(uint32_t dst, const void* src) {
    asm volatile("cp.async.cg.shared.global [%0], [%1], 16;" :: "r"(dst), "l"(src));
}
__device__ __forceinline__ void mma8(float* c, float a0, float a1, float a2, float a3,
                                     float b0, float b1) {
    asm volatile("mma.sync.aligned.m16n8k8.row.col.f32.tf32.tf32.f32 "
        "{%0,%1,%2,%3}, {%4,%5,%6,%7}, {%8,%9}, {%0,%1,%2,%3};"
        : "+f"(c[0]), "+f"(c[1]), "+f"(c[2]), "+f"(c[3])
        : "r"(__float_as_uint(a0)), "r"(__float_as_uint(a1)),
          "r"(__float_as_uint(a2)), "r"(__float_as_uint(a3)),
          "r"(__float_as_uint(b0)), "r"(__float_as_uint(b1)));
}

// ---------------- setup ----------------
__global__ void detect_kernel(const unsigned int* __restrict__ w) {
    int nz = 0;
    for (int i = threadIdx.x; i < 2048; i += blockDim.x)
        nz |= (w[2 * i + 1] != 0u);
    nz = __syncthreads_or(nz);
    if (threadIdx.x == 0) g_is64 = (nz == 0) ? 1 : 0;
}

__global__ void zero_cnt() {
    int i = blockIdx.x * blockDim.x + threadIdx.x;
    if (i < NN) g_icnt[i] = 0;
}

__global__ void convert_kernel(const void* __restrict__ ei) {
    int i = blockIdx.x * blockDim.x + threadIdx.x;
    if (i >= NE) return;
    int s, d;
    if (g_is64) {
        const long long* p = (const long long*)ei;
        s = (int)p[i]; d = (int)p[NE + i];
    } else {
        const int* p = (const int*)ei;
        s = p[i]; d = p[NE + i];
    }
    g_src[i] = s;
    g_dst[i] = d;
    atomicAdd(&g_icnt[d], 1);
}

__global__ void inv_kernel() {
    int i = blockIdx.x * blockDim.x + threadIdx.x;
    if (i < NN) g_inv[i] = 1.0f / fmaxf((float)g_icnt[i], 1.0f);
}

// ---------------- CSR build: 3-kernel exclusive scan + fill ----------------
__global__ void scan1() {                    // 391 blocks x 256
    __shared__ int sh[256];
    int i = blockIdx.x * 256 + threadIdx.x;
    sh[threadIdx.x] = (i < NN) ? g_icnt[i] : 0;
    for (int o = 128; o > 0; o >>= 1) {
        __syncthreads();
        if (threadIdx.x < o) sh[threadIdx.x] += sh[threadIdx.x + o];
    }
    if (threadIdx.x == 0) g_bsum[blockIdx.x] = sh[0];
}

__global__ void scan2() {                    // 1 block x 512
    __shared__ int sh[512];
    int t = threadIdx.x;
    sh[t] = (t < 391) ? g_bsum[t] : 0;
    __syncthreads();
    for (int o = 1; o < 512; o <<= 1) {
        int v = (t >= o) ? sh[t - o] : 0;
        __syncthreads();
        sh[t] += v;
        __syncthreads();
    }
    g_boff[t] = t ? sh[t - 1] : 0;
}

__global__ void scan3() {                    // 391 blocks x 256
    __shared__ int sh[256];
    int i = blockIdx.x * 256 + threadIdx.x;
    int v = (i < NN) ? g_icnt[i] : 0;
    sh[threadIdx.x] = v;
    __syncthreads();
    for (int o = 1; o < 256; o <<= 1) {
        int u = (threadIdx.x >= o) ? sh[threadIdx.x - o] : 0;
        __syncthreads();
        sh[threadIdx.x] += u;
        __syncthreads();
    }
    if (i < NN) {
        int excl = g_boff[blockIdx.x] + sh[threadIdx.x] - v;
        g_rowptr[i] = excl;
        g_cursor[i] = excl;
    }
}

__global__ void fill_kernel() {
    int i = blockIdx.x * blockDim.x + threadIdx.x;
    if (i >= NE) return;
    int slot = atomicAdd(&g_cursor[g_dst[i]], 1);
    g_adj[slot] = g_src[i];
}

// weights -> B-operand layout [n][k], tf32-rna
__global__ void prep_w1(const float* __restrict__ Wl, const float* __restrict__ Wr) {
    int tid = blockIdx.x * blockDim.x + threadIdx.x;   // 32768
    int k = tid >> 7, n = tid & 127;
    float v = (k < 128) ? Wl[k * 128 + n] : Wr[(k - 128) * 128 + n];
    g_W1t[n * 256 + k] = f2tf(v);
}

__global__ void prep_w2(const float* __restrict__ Wl, const float* __restrict__ Wr) {
    int tid = blockIdx.x * blockDim.x + threadIdx.x;   // 10240
    int k = tid / 80, n = tid - k * 80;
    float v = (n < 40) ? Wl[k * 40 + n] : Wr[k * 40 + (n - 40)];
    g_W2t[n * 128 + k] = f2tf(v);
}

// ---------------- gather layer 1: warp per node, 128 feats, fused mean ----------------
__global__ void __launch_bounds__(256) gather1_kernel(const float* __restrict__ x) {
    int node = (blockIdx.x * blockDim.x + threadIdx.x) >> 5;
    int lane = threadIdx.x & 31;
    if (node >= NN) return;
    int beg = g_rowptr[node];
    int end = beg + g_icnt[node];
    float4 acc = {0.f, 0.f, 0.f, 0.f};
    for (int j = beg; j < end; j += 32) {
        int n = min(32, end - j);
        int sidx = (j + lane < end) ? g_adj[j + lane] : 0;
        for (int k = 0; k < n; k++) {
            int s = __shfl_sync(0xffffffffu, sidx, k);
            float4 v = ((const float4*)x)[(size_t)s * 32 + lane];
            acc.x += v.x; acc.y += v.y; acc.z += v.z; acc.w += v.w;
        }
    }
    float iv = g_inv[node];
    acc.x *= iv; acc.y *= iv; acc.z *= iv; acc.w *= iv;
    ((float4*)g_mean)[(size_t)node * 32 + lane] = acc;
}

// ---------------- gather layer 2 + epilogue: out = mean(t2[nbrs]) + r2 + b2 ----------------
// 10 threads per node, each owns one float4 chunk of 40.
__global__ void __launch_bounds__(250) gather2_kernel(const float* __restrict__ b2,
                                                      float* __restrict__ out) {
    int i = blockIdx.x * blockDim.x + threadIdx.x;   // node*10 + c
    if (i >= NN * 10) return;
    int node = i / 10;
    int c = i - node * 10;
    int beg = g_rowptr[node];
    int end = beg + g_icnt[node];
    float4 acc = {0.f, 0.f, 0.f, 0.f};
    for (int j = beg; j < end; j++) {
        int s = g_adj[j];
        float4 v = ((const float4*)g_t2)[(size_t)s * 10 + c];
        acc.x += v.x; acc.y += v.y; acc.z += v.z; acc.w += v.w;
    }
    float iv = g_inv[node];
    float4 r = ((const float4*)g_r2)[i];
    float4 b = ((const float4*)b2)[c];
    float4 o;
    o.x = acc.x * iv + r.x + b.x;
    o.y = acc.y * iv + r.y + b.y;
    o.z = acc.z * iv + r.z + b.z;
    o.w = acc.w * iv + r.w + b.w;
    ((float4*)out)[i] = o;
}

// ---------------- GEMM1 (mma.sync tf32): h = relu([mean|x] @ W1cat + b1) ----------------
#define G1_SMEM (2 * 128 * LDA * 4 * 2 + 512)
__global__ void __launch_bounds__(256) gemm1_mma(const float* __restrict__ X,
                                                 const float* __restrict__ bias) {
    extern __shared__ float smem[];
    float* sA = smem;                       // 2 x 128 x LDA
    float* sB = sA + 2 * 128 * LDA;         // 2 x 128 x LDA
    float* sBias = sB + 2 * 128 * LDA;      // 128

    const int tid = threadIdx.x, lane = tid & 31, wid = tid >> 5;
    const int wm = wid & 3, wn = wid >> 2;
    const int row0 = blockIdx.x * 128;
    if (tid < 128) sBias[tid] = bias[tid];

    float acc[2][8][4];
    #pragma unroll
    for (int mt = 0; mt < 2; mt++)
        #pragma unroll
        for (int nt = 0; nt < 8; nt++)
            #pragma unroll
            for (int q = 0; q < 4; q++) acc[mt][nt][q] = 0.f;

    auto issue = [&](int c) {
        const float* asrc = (c < 4) ? g_mean : X;
        const int k0 = (c & 3) * 32;
        float* dA = sA + (c & 1) * (128 * LDA);
        float* dB = sB + (c & 1) * (128 * LDA);
        #pragma unroll
        for (int t = 0; t < 4; t++) {
            int i = tid + t * 256;
            int r = i >> 3, seg = i & 7;
            int grow = row0 + r;
            if (grow > NN - 1) grow = NN - 1;
            cp16((uint32_t)__cvta_generic_to_shared(dA + r * LDA + seg * 4),
                 asrc + (size_t)grow * 128 + k0 + seg * 4);
            cp16((uint32_t)__cvta_generic_to_shared(dB + r * LDA + seg * 4),
                 g_W1t + r * 256 + c * 32 + seg * 4);
        }
        asm volatile("cp.async.commit_group;" ::: "memory");
    };

    issue(0);
    for (int c = 0; c < 8; c++) {
        if (c < 7) {
            issue(c + 1);
            asm volatile("cp.async.wait_group 1;" ::: "memory");
        } else {
            asm volatile("cp.async.wait_group 0;" ::: "memory");
        }
        __syncthreads();
        const float* A = sA + (c & 1) * (128 * LDA);
        const float* B = sB + (c & 1) * (128 * LDA);
        #pragma unroll
        for (int ks = 0; ks < 4; ks++) {
            const int bk = ks * 8 + (lane & 3);
            float b0[8], b1[8];
            #pragma unroll
            for (int nt = 0; nt < 8; nt++) {
                int n = wn * 64 + nt * 8 + (lane >> 2);
                b0[nt] = B[n * LDA + bk];
                b1[nt] = B[n * LDA + bk + 4];
            }
            #pragma unroll
            for (int mt = 0; mt < 2; mt++) {
                int r = wm * 32 + mt * 16 + (lane >> 2);
                float a0 = f2tf(A[r * LDA + bk]);
                float a1 = f2tf(A[(r + 8) * LDA + bk]);
                float a2 = f2tf(A[r * LDA + bk + 4]);
                float a3 = f2tf(A[(r + 8) * LDA + bk + 4]);
                #pragma unroll
                for (int nt = 0; nt < 8; nt++)
                    mma8(acc[mt][nt], a0, a1, a2, a3, b0[nt], b1[nt]);
            }
        }
        __syncthreads();
    }

    #pragma unroll
    for (int mt = 0; mt < 2; mt++) {
        int r = row0 + wm * 32 + mt * 16 + (lane >> 2);
        #pragma unroll
        for (int nt = 0; nt < 8; nt++) {
            int cb = wn * 64 + nt * 8 + 2 * (lane & 3);
            if (r < NN) {
                float2 v;
                v.x = fmaxf(acc[mt][nt][0] + sBias[cb], 0.f);
                v.y = fmaxf(acc[mt][nt][1] + sBias[cb + 1], 0.f);
                *(float2*)(g_h + (size_t)r * 128 + cb) = v;
            }
            if (r + 8 < NN) {
                float2 v;
                v.x = fmaxf(acc[mt][nt][2] + sBias[cb], 0.f);
                v.y = fmaxf(acc[mt][nt][3] + sBias[cb + 1], 0.f);
                *(float2*)(g_h + (size_t)(r + 8) * 128 + cb) = v;
            }
        }
    }
}

// ---------------- GEMM2 (mma.sync tf32): [t2|r2] = h @ W2cat, N=80, K=128 ----------------
#define G2_SMEM ((2 * 128 * LDA + 2 * 80 * LDA) * 4)
__global__ void __launch_bounds__(256) gemm2_mma() {
    extern __shared__ float smem[];
    float* sA = smem;                       // 2 x 128 x LDA
    float* sB = sA + 2 * 128 * LDA;         // 2 x 80 x LDA

    const int tid = threadIdx.x, lane = tid & 31, wid = tid >> 5;
    const int row0 = blockIdx.x * 128;

    float acc[10][4];
    #pragma unroll
    for (int nt = 0; nt < 10; nt++)
        #pragma unroll
        for (int q = 0; q < 4; q++) acc[nt][q] = 0.f;

    auto issue = [&](int c) {
        const int k0 = c * 32;
        float* dA = sA + (c & 1) * (128 * LDA);
        float* dB = sB + (c & 1) * (80 * LDA);
        #pragma unroll
        for (int t = 0; t < 4; t++) {
            int i = tid + t * 256;
            int r = i >> 3, seg = i & 7;
            int grow = row0 + r;
            if (grow > NN - 1) grow = NN - 1;
            cp16((uint32_t)__cvta_generic_to_shared(dA + r * LDA + seg * 4),
                 g_h + (size_t)grow * 128 + k0 + seg * 4);
        }
        #pragma unroll
        for (int t = 0; t < 3; t++) {
            int i = tid + t * 256;
            if (i < 640) {
                int r = i >> 3, seg = i & 7;
                cp16((uint32_t)__cvta_generic_to_shared(dB + r * LDA + seg * 4),
                     g_W2t + r * 128 + k0 + seg * 4);
            }
        }
        asm volatile("cp.async.commit_group;" ::: "memory");
    };

    issue(0);
    for (int c = 0; c < 4; c++) {
        if (c < 3) {
            issue(c + 1);
            asm volatile("cp.async.wait_group 1;" ::: "memory");
        } else {
            asm volatile("cp.async.wait_group 0;" ::: "memory");
        }
        __syncthreads();
        const float* A = sA + (c & 1) * (128 * LDA);
        const float* B = sB + (c & 1) * (80 * LDA);
        #pragma unroll
        for (int ks = 0; ks < 4; ks++) {
            const int bk = ks * 8 + (lane & 3);
            float b0[10], b1[10];
            #pragma unroll
            for (int nt = 0; nt < 10; nt++) {
                int n = nt * 8 + (lane >> 2);
                b0[nt] = B[n * LDA + bk];
                b1[nt] = B[n * LDA + bk + 4];
            }
            int r = wid * 16 + (lane >> 2);
            float a0 = f2tf(A[r * LDA + bk]);
            float a1 = f2tf(A[(r + 8) * LDA + bk]);
            float a2 = f2tf(A[r * LDA + bk + 4]);
            float a3 = f2tf(A[(r + 8) * LDA + bk + 4]);
            #pragma unroll
            for (int nt = 0; nt < 10; nt++)
                mma8(acc[nt], a0, a1, a2, a3, b0[nt], b1[nt]);
        }
        __syncthreads();
    }

    int r = row0 + wid * 16 + (lane >> 2);
    #pragma unroll
    for (int nt = 0; nt < 10; nt++) {
        int cb = nt * 8 + 2 * (lane & 3);
        float* base0 = (cb < 40) ? g_t2 + (size_t)r * 40 + cb
                                 : g_r2 + (size_t)r * 40 + (cb - 40);
        float* base1 = (cb < 40) ? g_t2 + (size_t)(r + 8) * 40 + cb
                                 : g_r2 + (size_t)(r + 8) * 40 + (cb - 40);
        if (r < NN)     *(float2*)base0 = make_float2(acc[nt][0], acc[nt][1]);
        if (r + 8 < NN) *(float2*)base1 = make_float2(acc[nt][2], acc[nt][3]);
    }
}

// ---------------- launcher ----------------
extern "C" void kernel_launch(void* const* d_in, const int* in_sizes, int n_in,
                              void* d_out, int out_size) {
    const float* x    = (const float*)d_in[0];
    const void*  edge = d_in[1];
    const float* W1l  = (const float*)d_in[2];
    const float* W1r  = (const float*)d_in[3];
    const float* b1   = (const float*)d_in[4];
    const float* W2l  = (const float*)d_in[5];
    const float* W2r  = (const float*)d_in[6];
    const float* b2   = (const float*)d_in[7];
    float* out = (float*)d_out;

    static int attr_done = 0;
    if (!attr_done) {
        cudaFuncSetAttribute(gemm1_mma, cudaFuncAttributeMaxDynamicSharedMemorySize, G1_SMEM);
        cudaFuncSetAttribute(gemm2_mma, cudaFuncAttributeMaxDynamicSharedMemorySize, G2_SMEM);
        attr_done = 1;
    }

    const int NBLK = (NN + 255) / 256;       // 391

    detect_kernel<<<1, 256>>>((const unsigned int*)edge);
    zero_cnt<<<NBLK, 256>>>();
    convert_kernel<<<(NE + 255) / 256, 256>>>(edge);
    inv_kernel<<<NBLK, 256>>>();
    scan1<<<NBLK, 256>>>();
    scan2<<<1, 512>>>();
    scan3<<<NBLK, 256>>>();
    fill_kernel<<<(NE + 255) / 256, 256>>>();
    prep_w1<<<128, 256>>>(W1l, W1r);
    prep_w2<<<40, 256>>>(W2l, W2r);

    gather1_kernel<<<(NN * 32 + 255) / 256, 256>>>(x);
    gemm1_mma<<<(NN + 127) / 128, 256, G1_SMEM>>>(x, b1);
    gemm2_mma<<<(NN + 127) / 128, 256, G2_SMEM>>>();
    gather2_kernel<<<(NN * 10 + 249) / 250, 250>>>(b2, out);
}

// round 6
// speedup vs baseline: 4.2039x; 1.0492x over previous
#include <cuda_runtime.h>
#include <cstdint>

#define NN 100000
#define NE 800000
#define LDA 36
#define LDH 132

// ---------------- device scratch ----------------
__device__ float g_mean[(size_t)NN * 128];   // mean-aggregated x
__device__ float g_t2  [(size_t)NN * 40];    // h @ W2l
__device__ float g_r2  [(size_t)NN * 40];    // h @ W2r
__device__ int   g_icnt[NN];
__device__ float g_inv [NN];
__device__ int   g_rowptr[NN];
__device__ int   g_cursor[NN];
__device__ int   g_adj [NE];
__device__ int   g_src [NE];
__device__ int   g_dst [NE];
__device__ int   g_bsum[512];
__device__ int   g_is64;
__device__ float g_W1t[128 * 256];   // B layer1: [n=128][k=256], tf32-rna
__device__ float g_W2t[80 * 128];    // B layer2: [n=80][k=128], tf32-rna

// ---------------- helpers ----------------
__device__ __forceinline__ float f2tf(float f) {
    unsigned int r;
    asm("cvt.rna.tf32.f32 %0, %1;" : "=r"(r) : "f"(f));
    return __uint_as_float(r);
}
__device__ __forceinline__ void cp16(uint32_t dst, const void* src) {
    asm volatile("cp.async.cg.shared.global [%0], [%1], 16;" :: "r"(dst), "l"(src));
}
__device__ __forceinline__ void mma8(float* c, float a0, float a1, float a2, float a3,
                                     float b0, float b1) {
    asm volatile("mma.sync.aligned.m16n8k8.row.col.f32.tf32.tf32.f32 "
        "{%0,%1,%2,%3}, {%4,%5,%6,%7}, {%8,%9}, {%0,%1,%2,%3};"
        : "+f"(c[0]), "+f"(c[1]), "+f"(c[2]), "+f"(c[3])
        : "r"(__float_as_uint(a0)), "r"(__float_as_uint(a1)),
          "r"(__float_as_uint(a2)), "r"(__float_as_uint(a3)),
          "r"(__float_as_uint(b0)), "r"(__float_as_uint(b1)));
}

// ---------------- init: zero icnt everywhere, block 0 also detects dtype ----------------
__global__ void init_kernel(const unsigned int* __restrict__ w) {
    int i = blockIdx.x * blockDim.x + threadIdx.x;
    if (i < NN) g_icnt[i] = 0;
    if (blockIdx.x == 0) {
        int nz = 0;
        for (int t = threadIdx.x; t < 2048; t += blockDim.x)
            nz |= (w[2 * t + 1] != 0u);
        nz = __syncthreads_or(nz);
        if (threadIdx.x == 0) g_is64 = (nz == 0) ? 1 : 0;
    }
}

__global__ void convert_kernel(const void* __restrict__ ei) {
    int i = blockIdx.x * blockDim.x + threadIdx.x;
    if (i >= NE) return;
    int s, d;
    if (g_is64) {
        const long long* p = (const long long*)ei;
        s = (int)p[i]; d = (int)p[NE + i];
    } else {
        const int* p = (const int*)ei;
        s = p[i]; d = p[NE + i];
    }
    g_src[i] = s;
    g_dst[i] = d;
    atomicAdd(&g_icnt[d], 1);
}

// ---------------- CSR: block sums, then fused (scan bsums + local scan + inv) ----------------
__global__ void scan1() {                    // 391 blocks x 256
    __shared__ int sh[256];
    int i = blockIdx.x * 256 + threadIdx.x;
    sh[threadIdx.x] = (i < NN) ? g_icnt[i] : 0;
    for (int o = 128; o > 0; o >>= 1) {
        __syncthreads();
        if (threadIdx.x < o) sh[threadIdx.x] += sh[threadIdx.x + o];
    }
    if (threadIdx.x == 0) g_bsum[blockIdx.x] = sh[0];
}

__global__ void scan23() {                   // 391 blocks x 512
    __shared__ int sb[512];
    __shared__ int sh[256];
    int t = threadIdx.x;
    sb[t] = (t < 391) ? g_bsum[t] : 0;
    __syncthreads();
    #pragma unroll
    for (int o = 1; o < 512; o <<= 1) {
        int v = (t >= o) ? sb[t - o] : 0;
        __syncthreads();
        sb[t] += v;
        __syncthreads();
    }
    int blockoff = blockIdx.x ? sb[blockIdx.x - 1] : 0;

    int i = blockIdx.x * 256 + t;
    int v = 0;
    if (t < 256) {
        v = (i < NN) ? g_icnt[i] : 0;
        sh[t] = v;
    }
    __syncthreads();
    #pragma unroll
    for (int o = 1; o < 256; o <<= 1) {
        int u = (t < 256 && t >= o) ? sh[t - o] : 0;
        __syncthreads();
        if (t < 256) sh[t] += u;
        __syncthreads();
    }
    if (t < 256 && i < NN) {
        int excl = blockoff + sh[t] - v;
        g_rowptr[i] = excl;
        g_cursor[i] = excl;
        g_inv[i] = 1.0f / fmaxf((float)v, 1.0f);
    }
}

__global__ void fill_kernel() {
    int i = blockIdx.x * blockDim.x + threadIdx.x;
    if (i >= NE) return;
    int slot = atomicAdd(&g_cursor[g_dst[i]], 1);
    g_adj[slot] = g_src[i];
}

// weights -> B-operand layout [n][k], tf32-rna (one kernel, 168 blocks)
__global__ void prep_w(const float* __restrict__ W1l, const float* __restrict__ W1r,
                       const float* __restrict__ W2l, const float* __restrict__ W2r) {
    int tid = blockIdx.x * blockDim.x + threadIdx.x;
    if (tid < 32768) {
        int k = tid >> 7, n = tid & 127;
        float v = (k < 128) ? W1l[k * 128 + n] : W1r[(k - 128) * 128 + n];
        g_W1t[n * 256 + k] = f2tf(v);
    } else if (tid < 32768 + 10240) {
        int u = tid - 32768;
        int k = u / 80, n = u - k * 80;
        float v = (n < 40) ? W2l[k * 40 + n] : W2r[k * 40 + (n - 40)];
        g_W2t[n * 128 + k] = f2tf(v);
    }
}

// ---------------- gather layer 1: warp per node, MLP-4 unrolled ----------------
__global__ void __launch_bounds__(256) gather1_kernel(const float* __restrict__ x) {
    int node = (blockIdx.x * blockDim.x + threadIdx.x) >> 5;
    int lane = threadIdx.x & 31;
    if (node >= NN) return;
    int beg = g_rowptr[node];
    int end = beg + g_icnt[node];
    const float4* x4 = (const float4*)x;
    float4 acc = {0.f, 0.f, 0.f, 0.f};
    int j = beg;
    for (; j + 4 <= end; j += 4) {
        int s0 = __ldg(&g_adj[j]);
        int s1 = __ldg(&g_adj[j + 1]);
        int s2 = __ldg(&g_adj[j + 2]);
        int s3 = __ldg(&g_adj[j + 3]);
        float4 v0 = x4[(size_t)s0 * 32 + lane];
        float4 v1 = x4[(size_t)s1 * 32 + lane];
        float4 v2 = x4[(size_t)s2 * 32 + lane];
        float4 v3 = x4[(size_t)s3 * 32 + lane];
        acc.x += (v0.x + v1.x) + (v2.x + v3.x);
        acc.y += (v0.y + v1.y) + (v2.y + v3.y);
        acc.z += (v0.z + v1.z) + (v2.z + v3.z);
        acc.w += (v0.w + v1.w) + (v2.w + v3.w);
    }
    for (; j < end; j++) {
        int s = __ldg(&g_adj[j]);
        float4 v = x4[(size_t)s * 32 + lane];
        acc.x += v.x; acc.y += v.y; acc.z += v.z; acc.w += v.w;
    }
    float iv = g_inv[node];
    acc.x *= iv; acc.y *= iv; acc.z *= iv; acc.w *= iv;
    ((float4*)g_mean)[(size_t)node * 32 + lane] = acc;
}

// ---------------- gather layer 2 + epilogue: out = mean(t2[nbrs]) + r2 + b2 ----------------
__global__ void __launch_bounds__(250) gather2_kernel(const float* __restrict__ b2,
                                                      float* __restrict__ out) {
    int i = blockIdx.x * blockDim.x + threadIdx.x;   // node*10 + c
    if (i >= NN * 10) return;
    int node = i / 10;
    int c = i - node * 10;
    int beg = g_rowptr[node];
    int end = beg + g_icnt[node];
    const float4* t4 = (const float4*)g_t2;
    float4 acc = {0.f, 0.f, 0.f, 0.f};
    int j = beg;
    for (; j + 4 <= end; j += 4) {
        int s0 = __ldg(&g_adj[j]);
        int s1 = __ldg(&g_adj[j + 1]);
        int s2 = __ldg(&g_adj[j + 2]);
        int s3 = __ldg(&g_adj[j + 3]);
        float4 v0 = t4[(size_t)s0 * 10 + c];
        float4 v1 = t4[(size_t)s1 * 10 + c];
        float4 v2 = t4[(size_t)s2 * 10 + c];
        float4 v3 = t4[(size_t)s3 * 10 + c];
        acc.x += (v0.x + v1.x) + (v2.x + v3.x);
        acc.y += (v0.y + v1.y) + (v2.y + v3.y);
        acc.z += (v0.z + v1.z) + (v2.z + v3.z);
        acc.w += (v0.w + v1.w) + (v2.w + v3.w);
    }
    for (; j < end; j++) {
        int s = __ldg(&g_adj[j]);
        float4 v = t4[(size_t)s * 10 + c];
        acc.x += v.x; acc.y += v.y; acc.z += v.z; acc.w += v.w;
    }
    float iv = g_inv[node];
    float4 r = ((const float4*)g_r2)[i];
    float4 b = ((const float4*)b2)[c];
    float4 o;
    o.x = acc.x * iv + r.x + b.x;
    o.y = acc.y * iv + r.y + b.y;
    o.z = acc.z * iv + r.z + b.z;
    o.w = acc.w * iv + r.w + b.w;
    ((float4*)out)[i] = o;
}

// ---------------- fused GEMM: phase A h=relu([mean|x]@W1+b1) -> smem, phase B [t2|r2]=h@W2 ----------------
// smem: sA 2x128xLDA | sB 2x128xLDA | sH 128xLDH | sW2 80xLDH | bias 128
#define SM_A  0
#define SM_B  (2 * 128 * LDA)
#define SM_H  (SM_B + 2 * 128 * LDA)
#define SM_W2 (SM_H + 128 * LDH)
#define SM_BI (SM_W2 + 80 * LDH)
#define GF_SMEM ((SM_BI + 128) * 4)
__global__ void __launch_bounds__(256) gemm_fused(const float* __restrict__ X,
                                                  const float* __restrict__ bias) {
    extern __shared__ float smem[];
    float* sA = smem + SM_A;
    float* sB = smem + SM_B;
    float* sH = smem + SM_H;
    float* sW2 = smem + SM_W2;
    float* sBias = smem + SM_BI;

    const int tid = threadIdx.x, lane = tid & 31, wid = tid >> 5;
    const int wm = wid & 3, wn = wid >> 2;
    const int row0 = blockIdx.x * 128;
    if (tid < 128) sBias[tid] = bias[tid];

    // stage W2 [80][128] -> sW2 [80][LDH] (float4 rows; 2560 float4)
    {
        const float4* src = (const float4*)g_W2t;
        #pragma unroll
        for (int t = 0; t < 10; t++) {
            int i = tid + t * 256;
            int n = i >> 5, kq = i & 31;
            ((float4*)sW2)[n * (LDH / 4) + kq] = src[i];
        }
    }

    float acc[2][8][4];
    #pragma unroll
    for (int mt = 0; mt < 2; mt++)
        #pragma unroll
        for (int nt = 0; nt < 8; nt++)
            #pragma unroll
            for (int q = 0; q < 4; q++) acc[mt][nt][q] = 0.f;

    auto issue = [&](int c) {
        const float* asrc = (c < 4) ? g_mean : X;
        const int k0 = (c & 3) * 32;
        float* dA = sA + (c & 1) * (128 * LDA);
        float* dB = sB + (c & 1) * (128 * LDA);
        #pragma unroll
        for (int t = 0; t < 4; t++) {
            int i = tid + t * 256;
            int r = i >> 3, seg = i & 7;
            int grow = row0 + r;
            if (grow > NN - 1) grow = NN - 1;
            cp16((uint32_t)__cvta_generic_to_shared(dA + r * LDA + seg * 4),
                 asrc + (size_t)grow * 128 + k0 + seg * 4);
            cp16((uint32_t)__cvta_generic_to_shared(dB + r * LDA + seg * 4),
                 g_W1t + r * 256 + c * 32 + seg * 4);
        }
        asm volatile("cp.async.commit_group;" ::: "memory");
    };

    issue(0);
    for (int c = 0; c < 8; c++) {
        if (c < 7) {
            issue(c + 1);
            asm volatile("cp.async.wait_group 1;" ::: "memory");
        } else {
            asm volatile("cp.async.wait_group 0;" ::: "memory");
        }
        __syncthreads();
        const float* A = sA + (c & 1) * (128 * LDA);
        const float* B = sB + (c & 1) * (128 * LDA);
        #pragma unroll
        for (int ks = 0; ks < 4; ks++) {
            const int bk = ks * 8 + (lane & 3);
            float b0[8], b1[8];
            #pragma unroll
            for (int nt = 0; nt < 8; nt++) {
                int n = wn * 64 + nt * 8 + (lane >> 2);
                b0[nt] = B[n * LDA + bk];
                b1[nt] = B[n * LDA + bk + 4];
            }
            #pragma unroll
            for (int mt = 0; mt < 2; mt++) {
                int r = wm * 32 + mt * 16 + (lane >> 2);
                float a0 = f2tf(A[r * LDA + bk]);
                float a1 = f2tf(A[(r + 8) * LDA + bk]);
                float a2 = f2tf(A[r * LDA + bk + 4]);
                float a3 = f2tf(A[(r + 8) * LDA + bk + 4]);
                #pragma unroll
                for (int nt = 0; nt < 8; nt++)
                    mma8(acc[mt][nt], a0, a1, a2, a3, b0[nt], b1[nt]);
            }
        }
        __syncthreads();
    }

    // phase A epilogue: bias+relu -> sH
    #pragma unroll
    for (int mt = 0; mt < 2; mt++) {
        int r = wm * 32 + mt * 16 + (lane >> 2);
        #pragma unroll
        for (int nt = 0; nt < 8; nt++) {
            int cb = wn * 64 + nt * 8 + 2 * (lane & 3);
            sH[r * LDH + cb]           = fmaxf(acc[mt][nt][0] + sBias[cb], 0.f);
            sH[r * LDH + cb + 1]       = fmaxf(acc[mt][nt][1] + sBias[cb + 1], 0.f);
            sH[(r + 8) * LDH + cb]     = fmaxf(acc[mt][nt][2] + sBias[cb], 0.f);
            sH[(r + 8) * LDH + cb + 1] = fmaxf(acc[mt][nt][3] + sBias[cb + 1], 0.f);
        }
    }
    __syncthreads();

    // phase B: [t2|r2] = h @ W2cat (K=128 from smem)
    float acc2[10][4];
    #pragma unroll
    for (int nt = 0; nt < 10; nt++)
        #pragma unroll
        for (int q = 0; q < 4; q++) acc2[nt][q] = 0.f;

    const int r = wid * 16 + (lane >> 2);
    #pragma unroll
    for (int ks = 0; ks < 16; ks++) {
        const int bk = ks * 8 + (lane & 3);
        float a0 = f2tf(sH[r * LDH + bk]);
        float a1 = f2tf(sH[(r + 8) * LDH + bk]);
        float a2 = f2tf(sH[r * LDH + bk + 4]);
        float a3 = f2tf(sH[(r + 8) * LDH + bk + 4]);
        #pragma unroll
        for (int nt = 0; nt < 10; nt++) {
            int n = nt * 8 + (lane >> 2);
            float b0 = sW2[n * LDH + bk];
            float b1 = sW2[n * LDH + bk + 4];
            mma8(acc2[nt], a0, a1, a2, a3, b0, b1);
        }
    }

    int gr = row0 + r;
    #pragma unroll
    for (int nt = 0; nt < 10; nt++) {
        int cb = nt * 8 + 2 * (lane & 3);
        float* base0 = (cb < 40) ? g_t2 + (size_t)gr * 40 + cb
                                 : g_r2 + (size_t)gr * 40 + (cb - 40);
        float* base1 = (cb < 40) ? g_t2 + (size_t)(gr + 8) * 40 + cb
                                 : g_r2 + (size_t)(gr + 8) * 40 + (cb - 40);
        if (gr < NN)     *(float2*)base0 = make_float2(acc2[nt][0], acc2[nt][1]);
        if (gr + 8 < NN) *(float2*)base1 = make_float2(acc2[nt][2], acc2[nt][3]);
    }
}

// ---------------- launcher ----------------
extern "C" void kernel_launch(void* const* d_in, const int* in_sizes, int n_in,
                              void* d_out, int out_size) {
    const float* x    = (const float*)d_in[0];
    const void*  edge = d_in[1];
    const float* W1l  = (const float*)d_in[2];
    const float* W1r  = (const float*)d_in[3];
    const float* b1   = (const float*)d_in[4];
    const float* W2l  = (const float*)d_in[5];
    const float* W2r  = (const float*)d_in[6];
    const float* b2   = (const float*)d_in[7];
    float* out = (float*)d_out;

    static int attr_done = 0;
    if (!attr_done) {
        cudaFuncSetAttribute(gemm_fused, cudaFuncAttributeMaxDynamicSharedMemorySize, GF_SMEM);
        attr_done = 1;
    }

    const int NBLK = (NN + 255) / 256;       // 391

    init_kernel<<<NBLK, 256>>>((const unsigned int*)edge);
    convert_kernel<<<(NE + 255) / 256, 256>>>(edge);
    scan1<<<NBLK, 256>>>();
    scan23<<<NBLK, 512>>>();
    fill_kernel<<<(NE + 255) / 256, 256>>>();
    prep_w<<<168, 256>>>(W1l, W1r, W2l, W2r);

    gather1_kernel<<<(NN * 32 + 255) / 256, 256>>>(x);
    gemm_fused<<<(NN + 127) / 128, 256, GF_SMEM>>>(x, b1);
    gather2_kernel<<<(NN * 10 + 249) / 250, 250>>>(b2, out);
}